// round 16
// baseline (speedup 1.0000x reference)
#include <cuda_runtime.h>
#include <cuda_fp16.h>
#include <cstdint>
#include <math.h>

#define B_  16
#define C_  256
#define C4_ 64
#define H_  96
#define W_  96
#define HW_ 9216
#define EPSF 1e-5f

// ------------------------- scratch (static device memory; no allocs) -------
__device__ __align__(256) __half g_xh [B_*C_*HW_];    // x in fp16
__device__ float  g_h1 [B_*C4_*HW_];
__device__ float  g_h2 [B_*C_*HW_];
__device__ float  g_o2 [B_*C_*HW_];
__device__ __align__(256) __half g_h1g[B_*C4_*HW_];
__device__ __align__(256) __half g_qkv[B_*3*C_*HW_];
__device__ __align__(256) __half g_a  [B_*C_*HW_];
__device__ __align__(256) __half g_g  [B_*192*HW_];
__device__ float g_pooledx[B_*C_];
__device__ float g_route[B_*2];
__device__ float g_mean1[B_*C4_], g_var1[B_*C4_], g_ag1[B_*C4_], g_ab1[B_*C4_];
__device__ float g_mean2[B_*C_],  g_var2[B_*C_],  g_ag2[B_*C_],  g_ab2[B_*C_];
__device__ float g_bcomb[C_];
// pre-packed fp16 weights (exact smem layouts)
__device__ __align__(256) __half2 g_wpk1[1 * 16 * 9 * 64 * 8];   // conv1
__device__ __align__(256) __half2 g_wpk2[4 * 4 * 9 * 64 * 8];    // conv2
__device__ __align__(256) __half2 g_wpkq[768 * 8 * 16];          // qkv
__device__ __align__(256) __half2 g_wpkp[256 * 8 * 16];          // proj
__device__ __align__(256) __half2 g_wpkc[256 * 6 * 16];          // freq pw (scaled)

__device__ __forceinline__ float gelu_f(float v) {
    return 0.5f * v * (1.0f + erff(v * 0.70710678118654752440f));
}

// ------------------------- fp16 mma helpers --------------------------------
__device__ __forceinline__ void mma16(float* c, unsigned a0, unsigned a1,
                                      unsigned a2, unsigned a3,
                                      unsigned b0, unsigned b1) {
    asm volatile(
        "mma.sync.aligned.m16n8k16.row.col.f32.f16.f16.f32 "
        "{%0,%1,%2,%3},{%4,%5,%6,%7},{%8,%9},{%0,%1,%2,%3};"
        : "+f"(c[0]), "+f"(c[1]), "+f"(c[2]), "+f"(c[3])
        : "r"(a0), "r"(a1), "r"(a2), "r"(a3), "r"(b0), "r"(b1));
}
__device__ __forceinline__ unsigned packh2(float a, float b) {
    __half2 h = __floats2half2_rn(a, b);
    return reinterpret_cast<unsigned&>(h);
}
__device__ __forceinline__ int perm8inv(int j) { return ((j & 1) << 2) | (j >> 1); }

// pack 8 (k,k+8) pairs from two fp16 rows of 8 elements each
__device__ __forceinline__ void pack8(const __half* r0, const __half* r1, __half2* dst) {
    uint4 a = *(const uint4*)r0;
    uint4 b = *(const uint4*)r1;
    unsigned* d = (unsigned*)dst;
    d[0] = __byte_perm(a.x, b.x, 0x5410); d[1] = __byte_perm(a.x, b.x, 0x7632);
    d[2] = __byte_perm(a.y, b.y, 0x5410); d[3] = __byte_perm(a.y, b.y, 0x7632);
    d[4] = __byte_perm(a.z, b.z, 0x5410); d[5] = __byte_perm(a.z, b.z, 0x7632);
    d[6] = __byte_perm(a.w, b.w, 0x5410); d[7] = __byte_perm(a.w, b.w, 0x7632);
}

__device__ __forceinline__ void st2o(float* p, float x, float y) {
    *(float2*)p = make_float2(x, y);
}
__device__ __forceinline__ void st2o(__half* p, float x, float y) {
    *(__half2*)p = __floats2half2_rn(x, y);
}

// ------------------------- weight pre-pack kernels -------------------------
// conv: dst[(((coblk*(CIN/16)+chunk)*9 + kk)*64 + co)*8 + j],
//       pair = (w[coG][ci0+q][kk], w[coG][ci0+q+8][kk]), q = perm8inv(j)
__global__ void prepconv_k(const float* __restrict__ wt, __half2* __restrict__ dst,
                           int CIN, int COUT) {
    int total = (COUT >> 6) * (CIN >> 4) * 9 * 64 * 8;
    for (int idx = blockIdx.x * 256 + threadIdx.x; idx < total; idx += gridDim.x * 256) {
        int j = idx & 7;
        int rest = idx >> 3;
        int co = rest & 63; rest >>= 6;
        int kk = rest % 9; rest /= 9;
        int chunk = rest % (CIN >> 4);
        int coblk = rest / (CIN >> 4);
        int q = perm8inv(j);
        int coG = coblk * 64 + co;
        int ci = chunk * 16 + q;
        float a = wt[((size_t)coG * CIN + ci) * 9 + kk];
        float b = wt[((size_t)coG * CIN + ci + 8) * 9 + kk];
        dst[idx] = __floats2half2_rn(a, b);
    }
}
// gemm: dst[((co*(Cin/32)+k0c)*2 + kc)*8 + j], pair = (w[co][k], w[co][k+8])
__global__ void prepgemm_k(const float* __restrict__ wt, __half2* __restrict__ dst,
                           int Cin, int Cout) {
    int total = Cout * (Cin >> 5) * 16;
    for (int idx = blockIdx.x * 256 + threadIdx.x; idx < total; idx += gridDim.x * 256) {
        int j = idx & 7;
        int kc = (idx >> 3) & 1;
        int rest = idx >> 4;
        int k0c = rest % (Cin >> 5);
        int co = rest / (Cin >> 5);
        int k = k0c * 32 + kc * 16 + perm8inv(j);
        dst[idx] = __floats2half2_rn(wt[(size_t)co * Cin + k],
                                     wt[(size_t)co * Cin + k + 8]);
    }
}

// ------------------------- x -> fp16 + pooled mean (one pass) --------------
__global__ void xcvt_k(const float* __restrict__ x, __half* __restrict__ xh,
                       float* __restrict__ pooled) {
    int bc = blockIdx.x;
    const float* p = x + (size_t)bc * HW_;
    __half* o = xh + (size_t)bc * HW_;
    float s = 0.f;
    for (int i = threadIdx.x * 4; i < HW_; i += 1024) {
        float4 v = *(const float4*)(p + i);
        s += (v.x + v.y) + (v.z + v.w);
        *(__half2*)(o + i)     = __floats2half2_rn(v.x, v.y);
        *(__half2*)(o + i + 2) = __floats2half2_rn(v.z, v.w);
    }
    __shared__ float sh[8];
    #pragma unroll
    for (int of = 16; of; of >>= 1) s += __shfl_xor_sync(0xffffffffu, s, of);
    int w = threadIdx.x >> 5;
    if ((threadIdx.x & 31) == 0) sh[w] = s;
    __syncthreads();
    if (threadIdx.x == 0) {
        float S = 0.f;
        #pragma unroll
        for (int i = 0; i < 8; i++) S += sh[i];
        pooled[bc] = S * (1.0f / (float)HW_);
    }
}

// ------------------------- per-(b,c) mean / var reduction (float4) ---------
__global__ void reduce_stats_k(const float* __restrict__ in,
                               float* __restrict__ mean, float* __restrict__ var) {
    int bc = blockIdx.x;
    const float* p = in + (size_t)bc * HW_;
    float s = 0.f, ss = 0.f;
    for (int i = threadIdx.x * 4; i < HW_; i += 1024) {
        float4 v = *(const float4*)(p + i);
        s += (v.x + v.y) + (v.z + v.w);
        ss = fmaf(v.x, v.x, fmaf(v.y, v.y, fmaf(v.z, v.z, fmaf(v.w, v.w, ss))));
    }
    __shared__ float sh[8], sh2[8];
    #pragma unroll
    for (int o = 16; o; o >>= 1) {
        s  += __shfl_xor_sync(0xffffffffu, s, o);
        ss += __shfl_xor_sync(0xffffffffu, ss, o);
    }
    int w = threadIdx.x >> 5;
    if ((threadIdx.x & 31) == 0) { sh[w] = s; sh2[w] = ss; }
    __syncthreads();
    if (threadIdx.x == 0) {
        float S = 0.f, SS = 0.f;
        #pragma unroll
        for (int i = 0; i < 8; i++) { S += sh[i]; SS += sh2[i]; }
        float m = S * (1.0f / (float)HW_);
        mean[bc] = m;
        if (var) var[bc] = (SS - (float)HW_ * m * m) * (1.0f / (float)(HW_ - 1));
    }
}

// ------------------------- router ------------------------------------------
__global__ void router_k(const float* __restrict__ pooled,
                         const float* __restrict__ rw, const float* __restrict__ rb,
                         float* __restrict__ route) {
    int t = threadIdx.x;
    int b = t >> 1, j = t & 1;
    float acc = rb[j];
    for (int c = 0; c < C_; c++) acc = fmaf(rw[j * C_ + c], pooled[b * C_ + c], acc);
    float other = __shfl_xor_sync(0xffffffffu, acc, 1);
    float m = fmaxf(acc, other);
    float e = expf(acc - m), eo = expf(other - m);
    route[b * 2 + j] = e / (e + eo);
}

// ------------------------- 3x3 conv via fp16 implicit GEMM -----------------
// block 256, grid (48, COUT/64, B). 64 couts x (2 rows x 96) per CTA.
// weights pre-packed: wpk[(((coblk*(CIN/16)+chunk)*9+kk)*64+co)*8 + j]
template <int CIN, int COUT>
__global__ __launch_bounds__(256) void conv3x3_h(const __half* __restrict__ in,
                                                 const __half2* __restrict__ wpk,
                                                 const float* __restrict__ bias,
                                                 float* __restrict__ out) {
    __shared__ __half2 sW[9][64][12];
    __shared__ __half2 sI[4][8][108];
    int y0 = blockIdx.x * 2, co0 = blockIdx.y * 64, b = blockIdx.z;
    int tid = threadIdx.x, lane = tid & 31, wid = tid >> 5;
    int g = lane >> 2, tg = lane & 3;
    int warpM = (wid & 1) * 32, warpN = (wid >> 1) * 48;
    int rw = warpN / 96, xb = warpN % 96;

    float c[2][6][4] = {};

    for (int ci0 = 0; ci0 < CIN; ci0 += 16) {
        const __half2* wsrc = wpk
            + ((size_t)(blockIdx.y * (CIN >> 4) + (ci0 >> 4)) * 9) * 64 * 8;
        for (int idx = tid; idx < 1152; idx += 256) {
            int ck = idx >> 1, u4 = idx & 1;     // ck = kk*64 + co
            uint4 v = *(const uint4*)(wsrc + (size_t)ck * 8 + u4 * 4);
            *(uint4*)&sW[ck >> 6][ck & 63][u4 * 4] = v;
        }
        for (int idx = tid; idx < 4 * 8 * 98; idx += 256) {
            int ir = idx / 784, rem = idx - ir * 784;
            int q = rem / 98, xx = rem - q * 98;
            int gy = y0 - 1 + ir, gx = xx - 1;
            bool ok = ((unsigned)gy < 96u) && ((unsigned)gx < 96u);
            __half vA = ok ? in[((size_t)(b * CIN + ci0 + q)) * HW_ + gy * 96 + gx] : __half(0.f);
            __half vB = ok ? in[((size_t)(b * CIN + ci0 + q + 8)) * HW_ + gy * 96 + gx] : __half(0.f);
            sI[ir][q][xx] = __halves2half2(vA, vB);
        }
        __syncthreads();
        #pragma unroll
        for (int kk9 = 0; kk9 < 9; kk9++) {
            int kh = kk9 / 3, kw = kk9 % 3;
            unsigned a[2][4];
            #pragma unroll
            for (int mi = 0; mi < 2; mi++) {
                uint2 lo = *(const uint2*)&sW[kk9][warpM + mi * 16 + g][2 * tg];
                uint2 hi = *(const uint2*)&sW[kk9][warpM + mi * 16 + g + 8][2 * tg];
                a[mi][0] = lo.x; a[mi][1] = hi.x; a[mi][2] = lo.y; a[mi][3] = hi.y;
            }
            #pragma unroll
            for (int ni = 0; ni < 6; ni++) {
                int xx = xb + ni * 8 + g + kw;
                unsigned b0 = *(const unsigned*)&sI[rw + kh][tg][xx];
                unsigned b1 = *(const unsigned*)&sI[rw + kh][tg + 4][xx];
                #pragma unroll
                for (int mi = 0; mi < 2; mi++)
                    mma16(c[mi][ni], a[mi][0], a[mi][1], a[mi][2], a[mi][3], b0, b1);
            }
        }
        __syncthreads();
    }
    int y = y0 + rw;
    #pragma unroll
    for (int mi = 0; mi < 2; mi++) {
        int co = co0 + warpM + mi * 16 + g;
        float b0v = bias[co], b1v = bias[co + 8];
        #pragma unroll
        for (int ni = 0; ni < 6; ni++) {
            int x = xb + ni * 8 + 2 * tg;
            float* o0 = out + (size_t)(b * COUT + co) * HW_ + y * 96 + x;
            float* o1 = out + (size_t)(b * COUT + co + 8) * HW_ + y * 96 + x;
            *(float2*)o0 = make_float2(c[mi][ni][0] + b0v, c[mi][ni][1] + b0v);
            *(float2*)o1 = make_float2(c[mi][ni][2] + b1v, c[mi][ni][3] + b1v);
        }
    }
}

// ------------------------- 1x1 conv via fp16 GEMM --------------------------
// block 256, tile 64 cout x 256 spatial, K-chunk 32. grid (36, Cout/64, B).
// weights pre-packed: wpk[((co*(Cin/32)+k0c)*2 + kc)*8 + j]
template <typename TOUT, bool ACC>
__global__ __launch_bounds__(256) void gemm1x1_h(const __half* __restrict__ in,
                                                 const __half2* __restrict__ wpk,
                                                 const float* __restrict__ bias,
                                                 TOUT* __restrict__ out,
                                                 int Cin, int Cout) {
    __shared__ __half2 sA[64][20];
    __shared__ __half2 sB[16][264];
    int p0 = blockIdx.x * 256, co0 = blockIdx.y * 64, b = blockIdx.z;
    int tid = threadIdx.x, lane = tid & 31, wid = tid >> 5;
    int g = lane >> 2, tg = lane & 3;
    int warpM = (wid & 1) * 32, warpN = (wid >> 1) * 64;
    float c[2][8][4] = {};
    const __half* inb = in + (size_t)b * Cin * HW_;

    for (int k0 = 0; k0 < Cin; k0 += 32) {
        if (tid < 128) {
            int row = tid >> 1, kc = tid & 1;
            const __half2* src = wpk
                + (((size_t)(co0 + row) * (Cin >> 5) + (k0 >> 5)) * 2 + kc) * 8;
            *(uint4*)&sA[row][kc * 8]     = *(const uint4*)(src);
            *(uint4*)&sA[row][kc * 8 + 4] = *(const uint4*)(src + 4);
        }
        {
            int pr = tid >> 4, colc = tid & 15;
            int q = pr & 7, kc = pr >> 3;
            const __half* rbase = inb + (size_t)(k0 + kc * 16 + q) * HW_ + p0;
            #pragma unroll
            for (int seg = 0; seg < 2; seg++) {
                const __half* r0 = rbase + colc * 8 + seg * 128;
                const __half* r1 = r0 + (size_t)8 * HW_;
                __half2 tmp[8];
                pack8(r0, r1, tmp);
                *(uint4*)&sB[kc * 8 + q][colc * 8 + seg * 128]     = ((uint4*)tmp)[0];
                *(uint4*)&sB[kc * 8 + q][colc * 8 + seg * 128 + 4] = ((uint4*)tmp)[1];
            }
        }
        __syncthreads();
        #pragma unroll
        for (int kc = 0; kc < 2; kc++) {
            unsigned a[2][4];
            #pragma unroll
            for (int mi = 0; mi < 2; mi++) {
                uint2 lo = *(const uint2*)&sA[warpM + mi * 16 + g][kc * 8 + 2 * tg];
                uint2 hi = *(const uint2*)&sA[warpM + mi * 16 + g + 8][kc * 8 + 2 * tg];
                a[mi][0] = lo.x; a[mi][1] = hi.x; a[mi][2] = lo.y; a[mi][3] = hi.y;
            }
            #pragma unroll
            for (int ni = 0; ni < 8; ni++) {
                int n = warpN + ni * 8 + g;
                unsigned b0 = *(const unsigned*)&sB[kc * 8 + tg][n];
                unsigned b1 = *(const unsigned*)&sB[kc * 8 + tg + 4][n];
                #pragma unroll
                for (int mi = 0; mi < 2; mi++)
                    mma16(c[mi][ni], a[mi][0], a[mi][1], a[mi][2], a[mi][3], b0, b1);
            }
        }
        __syncthreads();
    }
    #pragma unroll
    for (int mi = 0; mi < 2; mi++) {
        int co = co0 + warpM + mi * 16 + g;
        float b0v = bias[co], b1v = bias[co + 8];
        #pragma unroll
        for (int ni = 0; ni < 8; ni++) {
            int p = p0 + warpN + ni * 8 + 2 * tg;
            TOUT* o0 = out + (size_t)(b * Cout + co) * HW_ + p;
            TOUT* o1 = out + (size_t)(b * Cout + co + 8) * HW_ + p;
            if (ACC) {
                float2 q0 = *(float2*)(void*)o0, q1 = *(float2*)(void*)o1;
                q0.x += c[mi][ni][0] + b0v; q0.y += c[mi][ni][1] + b0v;
                q1.x += c[mi][ni][2] + b1v; q1.y += c[mi][ni][3] + b1v;
                *(float2*)(void*)o0 = q0; *(float2*)(void*)o1 = q1;
            } else {
                st2o(o0, c[mi][ni][0] + b0v, c[mi][ni][1] + b0v);
                st2o(o1, c[mi][ni][2] + b1v, c[mi][ni][3] + b1v);
            }
        }
    }
}

// ------------------------- squeeze-excite (per batch) ----------------------
__global__ void se_k(const float* __restrict__ mean,
                     const float* __restrict__ s1w, const float* __restrict__ s1b,
                     const float* __restrict__ s2w, const float* __restrict__ s2b,
                     float* __restrict__ ag, float* __restrict__ ab, int Cc, int Hid) {
    int b = blockIdx.x, tid = threadIdx.x;
    __shared__ float pm[256];
    __shared__ float hh[64];
    for (int i = tid; i < Cc; i += 256) pm[i] = mean[b * Cc + i];
    __syncthreads();
    for (int o = tid; o < Hid; o += 256) {
        float a = s1b[o];
        for (int c = 0; c < Cc; c++) a = fmaf(s1w[o * Cc + c], pm[c], a);
        hh[o] = fmaxf(a, 0.f);
    }
    __syncthreads();
    for (int o = tid; o < 2 * Cc; o += 256) {
        float a = s2b[o];
        for (int k = 0; k < Hid; k++) a = fmaf(s2w[o * Hid + k], hh[k], a);
        if (o < Cc) ag[b * Cc + o] = a;
        else        ab[b * Cc + (o - Cc)] = a;
    }
}

// ------------------------- fused AFN + gelu (float4 in, half2 out) ---------
__global__ void afngelu_k(const float* __restrict__ h, const float* __restrict__ mean,
                          const float* __restrict__ var, const float* __restrict__ ag,
                          const float* __restrict__ ab, const float* __restrict__ gamma,
                          const float* __restrict__ beta, __half* __restrict__ out, int Cc) {
    int idx = (blockIdx.x * 256 + threadIdx.x) * 4;
    int bc = idx / HW_;
    int c = bc % Cc;
    float rs = rsqrtf(var[bc] + EPSF);
    float sc = (1.f + ag[bc]) * gamma[c] * rs;
    float sh = ab[bc] * beta[c] - sc * mean[bc];
    float4 v = *(const float4*)(h + idx);
    float y0 = gelu_f(fmaf(sc, v.x, sh));
    float y1 = gelu_f(fmaf(sc, v.y, sh));
    float y2 = gelu_f(fmaf(sc, v.z, sh));
    float y3 = gelu_f(fmaf(sc, v.w, sh));
    *(__half2*)(out + idx)     = __floats2half2_rn(y0, y1);
    *(__half2*)(out + idx + 2) = __floats2half2_rn(y2, y3);
}

// ------------------------- attention via fp16 MMA --------------------------
#define SQ_PITCH 52
#define SV_PITCH 104
__global__ __launch_bounds__(192) void attn_h(const __half* __restrict__ qkv,
                                              __half* __restrict__ aout) {
    extern __shared__ __half2 ash[];
    __half2* sQ = ash;
    __half2* sK = ash + 96 * SQ_PITCH;
    __half2* sV = ash + 2 * 96 * SQ_PITCH;
    int b = blockIdx.y, c = blockIdx.x;
    const __half* qp = qkv + ((size_t)b * 768 + c) * HW_;
    const __half* kp = qp + (size_t)256 * HW_;
    const __half* vp = qp + (size_t)512 * HW_;
    int tid = threadIdx.x, lane = tid & 31, wid = tid >> 5;
    int g = lane >> 2, tg = lane & 3;
    int rb = wid * 16;

    for (int u = tid; u < 576; u += 192) {
        int row = u / 6, grp = u % 6;
        const __half* sq = qp + row * 96 + grp * 16;
        uint4 x0 = *(const uint4*)sq, x1 = *(const uint4*)(sq + 8);
        *(uint4*)&sQ[row * SQ_PITCH + grp * 8]     = make_uint4(x0.x, x1.x, x0.y, x1.y);
        *(uint4*)&sQ[row * SQ_PITCH + grp * 8 + 4] = make_uint4(x0.z, x1.z, x0.w, x1.w);
        const __half* sk = kp + row * 96 + grp * 16;
        uint4 k0 = *(const uint4*)sk, k1 = *(const uint4*)(sk + 8);
        *(uint4*)&sK[row * SQ_PITCH + grp * 8]     = make_uint4(k0.x, k1.x, k0.y, k1.y);
        *(uint4*)&sK[row * SQ_PITCH + grp * 8 + 4] = make_uint4(k0.z, k1.z, k0.w, k1.w);
    }
    for (int u = tid; u < 288; u += 192) {
        int j2 = u / 6, grp = u % 6;
        const __half* r0 = vp + (2 * j2) * 96 + grp * 16;
        const __half* r1 = r0 + 96;
        uint4 a0 = *(const uint4*)r0, a1 = *(const uint4*)(r0 + 8);
        uint4 b0 = *(const uint4*)r1, b1 = *(const uint4*)(r1 + 8);
        unsigned o[16];
        o[0] = __byte_perm(a0.x, b0.x, 0x5410); o[1] = __byte_perm(a0.x, b0.x, 0x7632);
        o[2] = __byte_perm(a0.y, b0.y, 0x5410); o[3] = __byte_perm(a0.y, b0.y, 0x7632);
        o[4] = __byte_perm(a0.z, b0.z, 0x5410); o[5] = __byte_perm(a0.z, b0.z, 0x7632);
        o[6] = __byte_perm(a0.w, b0.w, 0x5410); o[7] = __byte_perm(a0.w, b0.w, 0x7632);
        o[8] = __byte_perm(a1.x, b1.x, 0x5410); o[9] = __byte_perm(a1.x, b1.x, 0x7632);
        o[10]= __byte_perm(a1.y, b1.y, 0x5410); o[11]= __byte_perm(a1.y, b1.y, 0x7632);
        o[12]= __byte_perm(a1.z, b1.z, 0x5410); o[13]= __byte_perm(a1.z, b1.z, 0x7632);
        o[14]= __byte_perm(a1.w, b1.w, 0x5410); o[15]= __byte_perm(a1.w, b1.w, 0x7632);
        unsigned* dst = (unsigned*)&sV[j2 * SV_PITCH + grp * 16];
        *(uint4*)(dst)      = make_uint4(o[0], o[1], o[2], o[3]);
        *(uint4*)(dst + 4)  = make_uint4(o[4], o[5], o[6], o[7]);
        *(uint4*)(dst + 8)  = make_uint4(o[8], o[9], o[10], o[11]);
        *(uint4*)(dst + 12) = make_uint4(o[12], o[13], o[14], o[15]);
    }
    __syncthreads();

    float sc[12][4] = {};
    #pragma unroll
    for (int kc = 0; kc < 6; kc++) {
        uint2 qa = *(const uint2*)&sQ[(rb + g) * SQ_PITCH + kc * 8 + 2 * tg];
        uint2 qb = *(const uint2*)&sQ[(rb + g + 8) * SQ_PITCH + kc * 8 + 2 * tg];
        #pragma unroll
        for (int ni = 0; ni < 12; ni++) {
            uint2 kb = *(const uint2*)&sK[(ni * 8 + g) * SQ_PITCH + kc * 8 + 2 * tg];
            mma16(sc[ni], qa.x, qb.x, qa.y, qb.y, kb.x, kb.y);
        }
    }
    float m1 = -1e30f, m2 = -1e30f;
    #pragma unroll
    for (int ni = 0; ni < 12; ni++) {
        m1 = fmaxf(m1, fmaxf(sc[ni][0], sc[ni][1]));
        m2 = fmaxf(m2, fmaxf(sc[ni][2], sc[ni][3]));
    }
    m1 = fmaxf(m1, __shfl_xor_sync(0xffffffffu, m1, 1));
    m1 = fmaxf(m1, __shfl_xor_sync(0xffffffffu, m1, 2));
    m2 = fmaxf(m2, __shfl_xor_sync(0xffffffffu, m2, 1));
    m2 = fmaxf(m2, __shfl_xor_sync(0xffffffffu, m2, 2));
    float s1 = 0.f, s2 = 0.f;
    #pragma unroll
    for (int ni = 0; ni < 12; ni++) {
        sc[ni][0] = __expf((sc[ni][0] - m1) * 0.0625f);
        sc[ni][1] = __expf((sc[ni][1] - m1) * 0.0625f);
        sc[ni][2] = __expf((sc[ni][2] - m2) * 0.0625f);
        sc[ni][3] = __expf((sc[ni][3] - m2) * 0.0625f);
        s1 += sc[ni][0] + sc[ni][1];
        s2 += sc[ni][2] + sc[ni][3];
    }
    s1 += __shfl_xor_sync(0xffffffffu, s1, 1);
    s1 += __shfl_xor_sync(0xffffffffu, s1, 2);
    s2 += __shfl_xor_sync(0xffffffffu, s2, 1);
    s2 += __shfl_xor_sync(0xffffffffu, s2, 2);
    float i1 = 1.f / s1, i2 = 1.f / s2;
    unsigned pa[12], pb[12];
    #pragma unroll
    for (int ni = 0; ni < 12; ni++) {
        pa[ni] = packh2(sc[ni][0] * i1, sc[ni][1] * i1);
        pb[ni] = packh2(sc[ni][2] * i2, sc[ni][3] * i2);
    }
    float oc_[12][4] = {};
    #pragma unroll
    for (int kc = 0; kc < 6; kc++) {
        unsigned a0 = pa[2 * kc], a1 = pb[2 * kc];
        unsigned a2 = pa[2 * kc + 1], a3 = pb[2 * kc + 1];
        #pragma unroll
        for (int ni = 0; ni < 12; ni++) {
            unsigned b0 = *(const unsigned*)&sV[(kc * 8 + tg) * SV_PITCH + ni * 8 + g];
            unsigned b1 = *(const unsigned*)&sV[(kc * 8 + tg + 4) * SV_PITCH + ni * 8 + g];
            mma16(oc_[ni], a0, a1, a2, a3, b0, b1);
        }
    }
    int n = c >> 5, d = c & 31, oc = d * 8 + n;
    __half* op = aout + (size_t)(b * C_ + oc) * HW_;
    #pragma unroll
    for (int ni = 0; ni < 12; ni++) {
        int col = ni * 8 + 2 * tg;
        *(__half2*)&op[(rb + g) * 96 + col]     = __floats2half2_rn(oc_[ni][0], oc_[ni][1]);
        *(__half2*)&op[(rb + g + 8) * 96 + col] = __floats2half2_rn(oc_[ni][2], oc_[ni][3]);
    }
}

// ------------------------- fused depthwise 3x3 (x3) + gelu (fp16 in/out) ---
__global__ __launch_bounds__(256) void dwgelu_k(const __half* __restrict__ x,
                                                const float* __restrict__ dww,
                                                const float* __restrict__ dwb,
                                                __half* __restrict__ g) {
    __shared__ float sIn[4][1156];
    __shared__ float sWd[3][36];
    __shared__ float sB[3];
    int tile = blockIdx.x, gch = blockIdx.y, b = blockIdx.z;
    int tx0 = (tile % 3) * 32, ty0 = (tile / 3) * 32;
    int tid = threadIdx.x, col = tid & 31, rowg = tid >> 5;

    for (int idx = tid; idx < 4 * 1156; idx += 256) {
        int ci = idx / 1156, rem = idx - ci * 1156;
        int r = rem / 34, cc = rem - r * 34;
        int gy = ty0 + r - 1, gx = tx0 + cc - 1;
        float v = 0.f;
        if (gy >= 0 && gy < H_ && gx >= 0 && gx < W_)
            v = __half2float(x[((size_t)(b * C_ + gch * 4 + ci)) * HW_ + gy * W_ + gx]);
        sIn[ci][rem] = v;
    }
    for (int idx = tid; idx < 108; idx += 256) {
        int i3 = idx / 36, rem = idx - i3 * 36;
        sWd[i3][rem] = dww[(size_t)(i3 * 64 + gch) * 36 + rem];
    }
    if (tid < 3) sB[tid] = dwb[tid * 64 + gch];
    __syncthreads();

    float acc[3][4];
    #pragma unroll
    for (int i3 = 0; i3 < 3; i3++)
        #pragma unroll
        for (int p = 0; p < 4; p++) acc[i3][p] = 0.f;

    #pragma unroll
    for (int ci = 0; ci < 4; ci++)
        #pragma unroll
        for (int kh = 0; kh < 3; kh++)
            #pragma unroll
            for (int kw = 0; kw < 3; kw++) {
                float iv[4];
                #pragma unroll
                for (int p = 0; p < 4; p++)
                    iv[p] = sIn[ci][(rowg + 8 * p + kh) * 34 + col + kw];
                #pragma unroll
                for (int i3 = 0; i3 < 3; i3++) {
                    float wv = sWd[i3][ci * 9 + kh * 3 + kw];
                    #pragma unroll
                    for (int p = 0; p < 4; p++) acc[i3][p] = fmaf(wv, iv[p], acc[i3][p]);
                }
            }
    #pragma unroll
    for (int i3 = 0; i3 < 3; i3++)
        #pragma unroll
        for (int p = 0; p < 4; p++)
            g[((size_t)(b * 192 + i3 * 64 + gch)) * HW_ + (ty0 + rowg + 8 * p) * W_ + tx0 + col]
                = __float2half_rn(gelu_f(acc[i3][p] + sB[i3]));
}

// ------------------------- freq prep: softmax folded, packed fp16 ----------
__global__ void freqprep_k(const float* __restrict__ fwraw, const float* __restrict__ pww,
                           const float* __restrict__ pwb, __half2* __restrict__ wpk,
                           float* __restrict__ bcomb) {
    float f0 = fwraw[0], f1 = fwraw[1], f2 = fwraw[2];
    float m = fmaxf(f0, fmaxf(f1, f2));
    float e0 = expf(f0 - m), e1 = expf(f1 - m), e2 = expf(f2 - m);
    float inv = 1.f / (e0 + e1 + e2);
    float fw[3] = {e0 * inv, e1 * inv, e2 * inv};
    const int total = 256 * 6 * 16;
    for (int idx = blockIdx.x * 256 + threadIdx.x; idx < total; idx += gridDim.x * 256) {
        int j = idx & 7;
        int kc = (idx >> 3) & 1;
        int rest = idx >> 4;
        int k0c = rest % 6;
        int co = rest / 6;
        int k = k0c * 32 + kc * 16 + perm8inv(j);
        int i = k >> 6, ci = k & 63, ci2 = (k + 8) & 63;
        float a = fw[i] * pww[((size_t)i * C_ + co) * 64 + ci];
        float b = fw[i] * pww[((size_t)i * C_ + co) * 64 + ci2];
        wpk[idx] = __floats2half2_rn(a, b);
    }
    if (blockIdx.x == 0)
        for (int idx = threadIdx.x; idx < C_; idx += 256)
            bcomb[idx] = fw[0] * pwb[idx] + fw[1] * pwb[C_ + idx] + fw[2] * pwb[2 * C_ + idx];
}

// ------------------------- final combine (float4) --------------------------
__global__ void final_k(const float* __restrict__ x, const float* __restrict__ h2,
                        const float* __restrict__ mean2, const float* __restrict__ var2,
                        const float* __restrict__ ag2, const float* __restrict__ ab2,
                        const float* __restrict__ gamma2, const float* __restrict__ beta2,
                        const float* __restrict__ o2, const float* __restrict__ route,
                        float* __restrict__ out) {
    int idx = (blockIdx.x * 256 + threadIdx.x) * 4;
    int bc = idx / HW_;
    int b = bc >> 8, c = bc & 255;
    float r0 = route[2 * b], r1 = route[2 * b + 1];
    float rs = rsqrtf(var2[bc] + EPSF);
    float sc = r0 * (1.f + ag2[bc]) * gamma2[c] * rs;
    float sh = r0 * (ab2[bc] * beta2[c]) - sc * mean2[bc];
    float4 xv = *(const float4*)(x + idx);
    float4 hv = *(const float4*)(h2 + idx);
    float4 ov = *(const float4*)(o2 + idx);
    float4 res;
    res.x = fmaf(sc, hv.x, fmaf(r1, ov.x, xv.x + sh));
    res.y = fmaf(sc, hv.y, fmaf(r1, ov.y, xv.y + sh));
    res.z = fmaf(sc, hv.z, fmaf(r1, ov.z, xv.z + sh));
    res.w = fmaf(sc, hv.w, fmaf(r1, ov.w, xv.w + sh));
    *(float4*)(out + idx) = res;
}

// ===========================================================================
extern "C" void kernel_launch(void* const* d_in, const int* in_sizes, int n_in,
                              void* d_out, int out_size) {
    const float* x     = (const float*)d_in[0];
    const float* w1    = (const float*)d_in[1];
    const float* b1    = (const float*)d_in[2];
    const float* g1    = (const float*)d_in[3];
    const float* be1   = (const float*)d_in[4];
    const float* s1w1  = (const float*)d_in[5];
    const float* s1b1  = (const float*)d_in[6];
    const float* s2w1  = (const float*)d_in[7];
    const float* s2b1  = (const float*)d_in[8];
    const float* w2    = (const float*)d_in[9];
    const float* b2    = (const float*)d_in[10];
    const float* g2    = (const float*)d_in[11];
    const float* be2   = (const float*)d_in[12];
    const float* s1w2  = (const float*)d_in[13];
    const float* s1b2  = (const float*)d_in[14];
    const float* s2w2  = (const float*)d_in[15];
    const float* s2b2  = (const float*)d_in[16];
    const float* qkvw  = (const float*)d_in[17];
    const float* qkvb  = (const float*)d_in[18];
    const float* projw = (const float*)d_in[19];
    const float* projb = (const float*)d_in[20];
    const float* dww   = (const float*)d_in[21];
    const float* dwb   = (const float*)d_in[22];
    const float* pww   = (const float*)d_in[23];
    const float* pwb   = (const float*)d_in[24];
    const float* fwr   = (const float*)d_in[25];
    const float* rw    = (const float*)d_in[26];
    const float* rb    = (const float*)d_in[27];
    float* out = (float*)d_out;

    float *h1, *h2, *o2, *pooledx, *route;
    float *mean1, *var1, *ag1, *ab1, *mean2, *var2, *ag2, *ab2, *bcomb;
    __half *xh, *h1g, *qkvh, *ah, *gh;
    __half2 *wpk1, *wpk2, *wpkq, *wpkp, *wpkc;
    cudaGetSymbolAddress((void**)&xh,  g_xh);
    cudaGetSymbolAddress((void**)&h1,  g_h1);
    cudaGetSymbolAddress((void**)&h2,  g_h2);
    cudaGetSymbolAddress((void**)&o2,  g_o2);
    cudaGetSymbolAddress((void**)&h1g, g_h1g);
    cudaGetSymbolAddress((void**)&qkvh, g_qkv);
    cudaGetSymbolAddress((void**)&ah,  g_a);
    cudaGetSymbolAddress((void**)&gh,  g_g);
    cudaGetSymbolAddress((void**)&pooledx, g_pooledx);
    cudaGetSymbolAddress((void**)&route,   g_route);
    cudaGetSymbolAddress((void**)&mean1, g_mean1);
    cudaGetSymbolAddress((void**)&var1,  g_var1);
    cudaGetSymbolAddress((void**)&ag1,   g_ag1);
    cudaGetSymbolAddress((void**)&ab1,   g_ab1);
    cudaGetSymbolAddress((void**)&mean2, g_mean2);
    cudaGetSymbolAddress((void**)&var2,  g_var2);
    cudaGetSymbolAddress((void**)&ag2,   g_ag2);
    cudaGetSymbolAddress((void**)&ab2,   g_ab2);
    cudaGetSymbolAddress((void**)&bcomb, g_bcomb);
    cudaGetSymbolAddress((void**)&wpk1,  g_wpk1);
    cudaGetSymbolAddress((void**)&wpk2,  g_wpk2);
    cudaGetSymbolAddress((void**)&wpkq,  g_wpkq);
    cudaGetSymbolAddress((void**)&wpkp,  g_wpkp);
    cudaGetSymbolAddress((void**)&wpkc,  g_wpkc);

    const int attnSmem = (2 * 96 * SQ_PITCH + 48 * SV_PITCH) * 4;
    cudaFuncSetAttribute(attn_h, cudaFuncAttributeMaxDynamicSharedMemorySize, attnSmem);

    static cudaStream_t s2 = nullptr;
    static cudaEvent_t evFork = nullptr, evJoin = nullptr;
    if (!s2) {
        cudaStreamCreateWithFlags(&s2, cudaStreamNonBlocking);
        cudaEventCreateWithFlags(&evFork, cudaEventDisableTiming);
        cudaEventCreateWithFlags(&evJoin, cudaEventDisableTiming);
    }

    // weight pre-pack + x -> fp16 + pooled mean; router  [stream 0]
    prepconv_k<<<72, 256>>>(w1, wpk1, 256, 64);
    prepconv_k<<<72, 256>>>(w2, wpk2, 64, 256);
    prepgemm_k<<<96, 256>>>(qkvw, wpkq, 256, 768);
    prepgemm_k<<<32, 256>>>(projw, wpkp, 256, 256);
    xcvt_k<<<B_ * C_, 256>>>(x, xh, pooledx);
    router_k<<<1, 32>>>(pooledx, rw, rb, route);

    // fork: branch 2 runs on s2, branch 1 stays on stream 0
    cudaEventRecord(evFork, 0);
    cudaStreamWaitEvent(s2, evFork, 0);

    // branch 1 [stream 0]
    conv3x3_h<256, 64><<<dim3(48, 1, B_), 256>>>(xh, wpk1, b1, h1);
    reduce_stats_k<<<B_ * C4_, 256>>>(h1, mean1, var1);
    se_k<<<B_, 256>>>(mean1, s1w1, s1b1, s2w1, s2b1, ag1, ab1, C4_, 16);
    afngelu_k<<<(B_ * C4_ * HW_) / 1024, 256>>>(h1, mean1, var1, ag1, ab1, g1, be1, h1g, C4_);
    conv3x3_h<64, 256><<<dim3(48, 4, B_), 256>>>(h1g, wpk2, b2, h2);
    reduce_stats_k<<<B_ * C_, 256>>>(h2, mean2, var2);
    se_k<<<B_, 256>>>(mean2, s1w2, s1b2, s2w2, s2b2, ag2, ab2, C_, 64);

    // branch 2 [stream s2]: attention + frequency decomposition
    gemm1x1_h<__half, false><<<dim3(36, 12, B_), 256, 0, s2>>>(xh, wpkq, qkvb, qkvh, 256, 768);
    attn_h<<<dim3(256, B_), 192, attnSmem, s2>>>(qkvh, ah);
    gemm1x1_h<float, false><<<dim3(36, 4, B_), 256, 0, s2>>>(ah, wpkp, projb, o2, 256, 256);
    freqprep_k<<<24, 256, 0, s2>>>(fwr, pww, pwb, wpkc, bcomb);
    dwgelu_k<<<dim3(9, 64, B_), 256, 0, s2>>>(xh, dww, dwb, gh);
    gemm1x1_h<float, true><<<dim3(36, 4, B_), 256, 0, s2>>>(gh, wpkc, bcomb, o2, 192, 256);

    // join: stream 0 waits for branch 2 before final combine
    cudaEventRecord(evJoin, s2);
    cudaStreamWaitEvent(0, evJoin, 0);

    // final combine [stream 0]
    final_k<<<(B_ * C_ * HW_) / 1024, 256>>>(x, h2, mean2, var2, ag2, ab2, g2, be2,
                                             o2, route, out);
}

// round 17
// speedup vs baseline: 1.3923x; 1.3923x over previous
#include <cuda_runtime.h>
#include <cuda_fp16.h>
#include <cstdint>
#include <math.h>

#define B_  16
#define C_  256
#define C4_ 64
#define H_  96
#define W_  96
#define HW_ 9216
#define EPSF 1e-5f

// ------------------------- scratch (static device memory; no allocs) -------
__device__ __align__(256) __half g_xh [B_*C_*HW_];    // x in fp16
__device__ float  g_h1 [B_*C4_*HW_];
__device__ float  g_h2 [B_*C_*HW_];
__device__ float  g_o2 [B_*C_*HW_];
__device__ __align__(256) __half g_h1g[B_*C4_*HW_];
__device__ __align__(256) __half g_qkv[B_*3*C_*HW_];
__device__ __align__(256) __half g_a  [B_*C_*HW_];
__device__ __align__(256) __half g_g  [B_*192*HW_];
__device__ float g_pooledx[B_*C_];
__device__ float g_route[B_*2];
__device__ float g_mean1[B_*C4_], g_var1[B_*C4_], g_ag1[B_*C4_], g_ab1[B_*C4_];
__device__ float g_mean2[B_*C_],  g_var2[B_*C_],  g_ag2[B_*C_],  g_ab2[B_*C_];
__device__ float g_bcomb[C_];
// packed fp16 gemm weights: [((co*(Cin/32)+k0c)*2 + kc)*8 + j]
__device__ __align__(256) __half2 g_wpkq[768 * 8 * 16];          // qkv
__device__ __align__(256) __half2 g_wpkp[256 * 8 * 16];          // proj
__device__ __align__(256) __half2 g_wpkc[256 * 6 * 16];          // freq pw (scaled)

__device__ __forceinline__ float gelu_f(float v) {
    return 0.5f * v * (1.0f + erff(v * 0.70710678118654752440f));
}

// ------------------------- fp16 mma helpers --------------------------------
__device__ __forceinline__ void mma16(float* c, unsigned a0, unsigned a1,
                                      unsigned a2, unsigned a3,
                                      unsigned b0, unsigned b1) {
    asm volatile(
        "mma.sync.aligned.m16n8k16.row.col.f32.f16.f16.f32 "
        "{%0,%1,%2,%3},{%4,%5,%6,%7},{%8,%9},{%0,%1,%2,%3};"
        : "+f"(c[0]), "+f"(c[1]), "+f"(c[2]), "+f"(c[3])
        : "r"(a0), "r"(a1), "r"(a2), "r"(a3), "r"(b0), "r"(b1));
}
__device__ __forceinline__ unsigned packh2(float a, float b) {
    __half2 h = __floats2half2_rn(a, b);
    return reinterpret_cast<unsigned&>(h);
}
__device__ __forceinline__ int perm8(int q) { return ((q & 3) << 1) | (q >> 2); }
__device__ __forceinline__ int perm8inv(int j) { return ((j & 1) << 2) | (j >> 1); }

// pack 8 (k,k+8) pairs from two fp16 rows of 8 elements each
__device__ __forceinline__ void pack8(const __half* r0, const __half* r1, __half2* dst) {
    uint4 a = *(const uint4*)r0;
    uint4 b = *(const uint4*)r1;
    unsigned* d = (unsigned*)dst;
    d[0] = __byte_perm(a.x, b.x, 0x5410); d[1] = __byte_perm(a.x, b.x, 0x7632);
    d[2] = __byte_perm(a.y, b.y, 0x5410); d[3] = __byte_perm(a.y, b.y, 0x7632);
    d[4] = __byte_perm(a.z, b.z, 0x5410); d[5] = __byte_perm(a.z, b.z, 0x7632);
    d[6] = __byte_perm(a.w, b.w, 0x5410); d[7] = __byte_perm(a.w, b.w, 0x7632);
}

__device__ __forceinline__ void st2o(float* p, float x, float y) {
    *(float2*)p = make_float2(x, y);
}
__device__ __forceinline__ void st2o(__half* p, float x, float y) {
    *(__half2*)p = __floats2half2_rn(x, y);
}

// ------------------------- gemm weight pre-pack ----------------------------
// dst[((co*(Cin/32)+k0c)*2 + kc)*8 + j], pair = (w[co][k], w[co][k+8]),
// k = k0c*32 + kc*16 + perm8inv(j)
__global__ void prepgemm_k(const float* __restrict__ wt, __half2* __restrict__ dst,
                           int Cin, int Cout) {
    int total = Cout * (Cin >> 5) * 16;
    for (int idx = blockIdx.x * 256 + threadIdx.x; idx < total; idx += gridDim.x * 256) {
        int j = idx & 7;
        int kc = (idx >> 3) & 1;
        int rest = idx >> 4;
        int k0c = rest % (Cin >> 5);
        int co = rest / (Cin >> 5);
        int k = k0c * 32 + kc * 16 + perm8inv(j);
        dst[idx] = __floats2half2_rn(wt[(size_t)co * Cin + k],
                                     wt[(size_t)co * Cin + k + 8]);
    }
}

// ------------------------- x -> fp16 + pooled mean (one pass) --------------
__global__ void xcvt_k(const float* __restrict__ x, __half* __restrict__ xh,
                       float* __restrict__ pooled) {
    int bc = blockIdx.x;
    const float* p = x + (size_t)bc * HW_;
    __half* o = xh + (size_t)bc * HW_;
    float s = 0.f;
    for (int i = threadIdx.x * 4; i < HW_; i += 1024) {
        float4 v = *(const float4*)(p + i);
        s += (v.x + v.y) + (v.z + v.w);
        *(__half2*)(o + i)     = __floats2half2_rn(v.x, v.y);
        *(__half2*)(o + i + 2) = __floats2half2_rn(v.z, v.w);
    }
    __shared__ float sh[8];
    #pragma unroll
    for (int of = 16; of; of >>= 1) s += __shfl_xor_sync(0xffffffffu, s, of);
    int w = threadIdx.x >> 5;
    if ((threadIdx.x & 31) == 0) sh[w] = s;
    __syncthreads();
    if (threadIdx.x == 0) {
        float S = 0.f;
        #pragma unroll
        for (int i = 0; i < 8; i++) S += sh[i];
        pooled[bc] = S * (1.0f / (float)HW_);
    }
}

// ------------------------- per-(b,c) mean / var reduction (float4) ---------
__global__ void reduce_stats_k(const float* __restrict__ in,
                               float* __restrict__ mean, float* __restrict__ var) {
    int bc = blockIdx.x;
    const float* p = in + (size_t)bc * HW_;
    float s = 0.f, ss = 0.f;
    for (int i = threadIdx.x * 4; i < HW_; i += 1024) {
        float4 v = *(const float4*)(p + i);
        s += (v.x + v.y) + (v.z + v.w);
        ss = fmaf(v.x, v.x, fmaf(v.y, v.y, fmaf(v.z, v.z, fmaf(v.w, v.w, ss))));
    }
    __shared__ float sh[8], sh2[8];
    #pragma unroll
    for (int o = 16; o; o >>= 1) {
        s  += __shfl_xor_sync(0xffffffffu, s, o);
        ss += __shfl_xor_sync(0xffffffffu, ss, o);
    }
    int w = threadIdx.x >> 5;
    if ((threadIdx.x & 31) == 0) { sh[w] = s; sh2[w] = ss; }
    __syncthreads();
    if (threadIdx.x == 0) {
        float S = 0.f, SS = 0.f;
        #pragma unroll
        for (int i = 0; i < 8; i++) { S += sh[i]; SS += sh2[i]; }
        float m = S * (1.0f / (float)HW_);
        mean[bc] = m;
        if (var) var[bc] = (SS - (float)HW_ * m * m) * (1.0f / (float)(HW_ - 1));
    }
}

// ------------------------- router ------------------------------------------
__global__ void router_k(const float* __restrict__ pooled,
                         const float* __restrict__ rw, const float* __restrict__ rb,
                         float* __restrict__ route) {
    int t = threadIdx.x;
    int b = t >> 1, j = t & 1;
    float acc = rb[j];
    for (int c = 0; c < C_; c++) acc = fmaf(rw[j * C_ + c], pooled[b * C_ + c], acc);
    float other = __shfl_xor_sync(0xffffffffu, acc, 1);
    float m = fmaxf(acc, other);
    float e = expf(acc - m), eo = expf(other - m);
    route[b * 2 + j] = e / (e + eo);
}

// ------------------------- 3x3 conv via fp16 implicit GEMM (R15 verbatim) --
template <int CIN, int COUT>
__global__ __launch_bounds__(256) void conv3x3_h(const __half* __restrict__ in,
                                                 const float* __restrict__ wt,
                                                 const float* __restrict__ bias,
                                                 float* __restrict__ out) {
    __shared__ __half2 sW[9][64][10];
    __shared__ __half2 sI[4][8][108];
    int y0 = blockIdx.x * 2, co0 = blockIdx.y * 64, b = blockIdx.z;
    int tid = threadIdx.x, lane = tid & 31, wid = tid >> 5;
    int g = lane >> 2, tg = lane & 3;
    int warpM = (wid & 1) * 32, warpN = (wid >> 1) * 48;
    int rw = warpN / 96, xb = warpN % 96;

    float c[2][6][4] = {};

    for (int ci0 = 0; ci0 < CIN; ci0 += 16) {
        for (int u = tid; u < 512; u += 256) {
            int co = u >> 3, q = u & 7;
            const float* wpA = wt + ((size_t)(co0 + co) * CIN + ci0 + q) * 9;
            const float* wpB = wpA + 8 * 9;
            #pragma unroll
            for (int kk = 0; kk < 9; kk++)
                sW[kk][co][perm8(q)] = __floats2half2_rn(wpA[kk], wpB[kk]);
        }
        for (int idx = tid; idx < 4 * 8 * 98; idx += 256) {
            int ir = idx / 784, rem = idx - ir * 784;
            int q = rem / 98, xx = rem - q * 98;
            int gy = y0 - 1 + ir, gx = xx - 1;
            bool ok = ((unsigned)gy < 96u) && ((unsigned)gx < 96u);
            __half vA = ok ? in[((size_t)(b * CIN + ci0 + q)) * HW_ + gy * 96 + gx] : __half(0.f);
            __half vB = ok ? in[((size_t)(b * CIN + ci0 + q + 8)) * HW_ + gy * 96 + gx] : __half(0.f);
            sI[ir][q][xx] = __halves2half2(vA, vB);
        }
        __syncthreads();
        #pragma unroll
        for (int kk9 = 0; kk9 < 9; kk9++) {
            int kh = kk9 / 3, kw = kk9 % 3;
            unsigned a[2][4];
            #pragma unroll
            for (int mi = 0; mi < 2; mi++) {
                uint2 lo = *(const uint2*)&sW[kk9][warpM + mi * 16 + g][2 * tg];
                uint2 hi = *(const uint2*)&sW[kk9][warpM + mi * 16 + g + 8][2 * tg];
                a[mi][0] = lo.x; a[mi][1] = hi.x; a[mi][2] = lo.y; a[mi][3] = hi.y;
            }
            #pragma unroll
            for (int ni = 0; ni < 6; ni++) {
                int xx = xb + ni * 8 + g + kw;
                unsigned b0 = *(const unsigned*)&sI[rw + kh][tg][xx];
                unsigned b1 = *(const unsigned*)&sI[rw + kh][tg + 4][xx];
                #pragma unroll
                for (int mi = 0; mi < 2; mi++)
                    mma16(c[mi][ni], a[mi][0], a[mi][1], a[mi][2], a[mi][3], b0, b1);
            }
        }
        __syncthreads();
    }
    int y = y0 + rw;
    #pragma unroll
    for (int mi = 0; mi < 2; mi++) {
        int co = co0 + warpM + mi * 16 + g;
        float b0v = bias[co], b1v = bias[co + 8];
        #pragma unroll
        for (int ni = 0; ni < 6; ni++) {
            int x = xb + ni * 8 + 2 * tg;
            float* o0 = out + (size_t)(b * COUT + co) * HW_ + y * 96 + x;
            float* o1 = out + (size_t)(b * COUT + co + 8) * HW_ + y * 96 + x;
            *(float2*)o0 = make_float2(c[mi][ni][0] + b0v, c[mi][ni][1] + b0v);
            *(float2*)o1 = make_float2(c[mi][ni][2] + b1v, c[mi][ni][3] + b1v);
        }
    }
}

// ------------------------- 1x1 conv via fp16 GEMM (packed weights) ---------
// block 256, tile 64 cout x 256 spatial, K-chunk 32. grid (36, Cout/64, B).
// sA pitch 18 (unchanged from R15); weight fill = 2 LDG.128 + 4 STS.64.
template <typename TOUT, bool ACC>
__global__ __launch_bounds__(256) void gemm1x1_h(const __half* __restrict__ in,
                                                 const __half2* __restrict__ wpk,
                                                 const float* __restrict__ bias,
                                                 TOUT* __restrict__ out,
                                                 int Cin, int Cout) {
    __shared__ __half2 sA[64][18];
    __shared__ __half2 sB[16][264];
    int p0 = blockIdx.x * 256, co0 = blockIdx.y * 64, b = blockIdx.z;
    int tid = threadIdx.x, lane = tid & 31, wid = tid >> 5;
    int g = lane >> 2, tg = lane & 3;
    int warpM = (wid & 1) * 32, warpN = (wid >> 1) * 64;
    float c[2][8][4] = {};
    const __half* inb = in + (size_t)b * Cin * HW_;

    for (int k0 = 0; k0 < Cin; k0 += 32) {
        if (tid < 128) {
            int row = tid >> 1, kc = tid & 1;
            const __half2* src = wpk
                + (((size_t)(co0 + row) * (Cin >> 5) + (k0 >> 5)) * 2 + kc) * 8;
            uint4 v0 = *(const uint4*)src;
            uint4 v1 = *(const uint4*)(src + 4);
            uint2* d = (uint2*)&sA[row][kc * 8];
            d[0] = make_uint2(v0.x, v0.y); d[1] = make_uint2(v0.z, v0.w);
            d[2] = make_uint2(v1.x, v1.y); d[3] = make_uint2(v1.z, v1.w);
        }
        {
            int pr = tid >> 4, colc = tid & 15;
            int q = pr & 7, kc = pr >> 3;
            const __half* rbase = inb + (size_t)(k0 + kc * 16 + q) * HW_ + p0;
            #pragma unroll
            for (int seg = 0; seg < 2; seg++) {
                const __half* r0 = rbase + colc * 8 + seg * 128;
                const __half* r1 = r0 + (size_t)8 * HW_;
                __half2 tmp[8];
                pack8(r0, r1, tmp);
                *(uint4*)&sB[kc * 8 + q][colc * 8 + seg * 128]     = ((uint4*)tmp)[0];
                *(uint4*)&sB[kc * 8 + q][colc * 8 + seg * 128 + 4] = ((uint4*)tmp)[1];
            }
        }
        __syncthreads();
        #pragma unroll
        for (int kc = 0; kc < 2; kc++) {
            unsigned a[2][4];
            #pragma unroll
            for (int mi = 0; mi < 2; mi++) {
                uint2 lo = *(const uint2*)&sA[warpM + mi * 16 + g][kc * 8 + 2 * tg];
                uint2 hi = *(const uint2*)&sA[warpM + mi * 16 + g + 8][kc * 8 + 2 * tg];
                a[mi][0] = lo.x; a[mi][1] = hi.x; a[mi][2] = lo.y; a[mi][3] = hi.y;
            }
            #pragma unroll
            for (int ni = 0; ni < 8; ni++) {
                int n = warpN + ni * 8 + g;
                unsigned b0 = *(const unsigned*)&sB[kc * 8 + tg][n];
                unsigned b1 = *(const unsigned*)&sB[kc * 8 + tg + 4][n];
                #pragma unroll
                for (int mi = 0; mi < 2; mi++)
                    mma16(c[mi][ni], a[mi][0], a[mi][1], a[mi][2], a[mi][3], b0, b1);
            }
        }
        __syncthreads();
    }
    #pragma unroll
    for (int mi = 0; mi < 2; mi++) {
        int co = co0 + warpM + mi * 16 + g;
        float b0v = bias[co], b1v = bias[co + 8];
        #pragma unroll
        for (int ni = 0; ni < 8; ni++) {
            int p = p0 + warpN + ni * 8 + 2 * tg;
            TOUT* o0 = out + (size_t)(b * Cout + co) * HW_ + p;
            TOUT* o1 = out + (size_t)(b * Cout + co + 8) * HW_ + p;
            if (ACC) {
                float2 q0 = *(float2*)(void*)o0, q1 = *(float2*)(void*)o1;
                q0.x += c[mi][ni][0] + b0v; q0.y += c[mi][ni][1] + b0v;
                q1.x += c[mi][ni][2] + b1v; q1.y += c[mi][ni][3] + b1v;
                *(float2*)(void*)o0 = q0; *(float2*)(void*)o1 = q1;
            } else {
                st2o(o0, c[mi][ni][0] + b0v, c[mi][ni][1] + b0v);
                st2o(o1, c[mi][ni][2] + b1v, c[mi][ni][3] + b1v);
            }
        }
    }
}

// ------------------------- squeeze-excite (per batch) ----------------------
__global__ void se_k(const float* __restrict__ mean,
                     const float* __restrict__ s1w, const float* __restrict__ s1b,
                     const float* __restrict__ s2w, const float* __restrict__ s2b,
                     float* __restrict__ ag, float* __restrict__ ab, int Cc, int Hid) {
    int b = blockIdx.x, tid = threadIdx.x;
    __shared__ float pm[256];
    __shared__ float hh[64];
    for (int i = tid; i < Cc; i += 256) pm[i] = mean[b * Cc + i];
    __syncthreads();
    for (int o = tid; o < Hid; o += 256) {
        float a = s1b[o];
        for (int c = 0; c < Cc; c++) a = fmaf(s1w[o * Cc + c], pm[c], a);
        hh[o] = fmaxf(a, 0.f);
    }
    __syncthreads();
    for (int o = tid; o < 2 * Cc; o += 256) {
        float a = s2b[o];
        for (int k = 0; k < Hid; k++) a = fmaf(s2w[o * Hid + k], hh[k], a);
        if (o < Cc) ag[b * Cc + o] = a;
        else        ab[b * Cc + (o - Cc)] = a;
    }
}

// ------------------------- fused AFN + gelu (float4 in, half2 out) ---------
__global__ void afngelu_k(const float* __restrict__ h, const float* __restrict__ mean,
                          const float* __restrict__ var, const float* __restrict__ ag,
                          const float* __restrict__ ab, const float* __restrict__ gamma,
                          const float* __restrict__ beta, __half* __restrict__ out, int Cc) {
    int idx = (blockIdx.x * 256 + threadIdx.x) * 4;
    int bc = idx / HW_;
    int c = bc % Cc;
    float rs = rsqrtf(var[bc] + EPSF);
    float sc = (1.f + ag[bc]) * gamma[c] * rs;
    float sh = ab[bc] * beta[c] - sc * mean[bc];
    float4 v = *(const float4*)(h + idx);
    float y0 = gelu_f(fmaf(sc, v.x, sh));
    float y1 = gelu_f(fmaf(sc, v.y, sh));
    float y2 = gelu_f(fmaf(sc, v.z, sh));
    float y3 = gelu_f(fmaf(sc, v.w, sh));
    *(__half2*)(out + idx)     = __floats2half2_rn(y0, y1);
    *(__half2*)(out + idx + 2) = __floats2half2_rn(y2, y3);
}

// ------------------------- attention via fp16 MMA --------------------------
#define SQ_PITCH 52
#define SV_PITCH 104
__global__ __launch_bounds__(192) void attn_h(const __half* __restrict__ qkv,
                                              __half* __restrict__ aout) {
    extern __shared__ __half2 ash[];
    __half2* sQ = ash;
    __half2* sK = ash + 96 * SQ_PITCH;
    __half2* sV = ash + 2 * 96 * SQ_PITCH;
    int b = blockIdx.y, c = blockIdx.x;
    const __half* qp = qkv + ((size_t)b * 768 + c) * HW_;
    const __half* kp = qp + (size_t)256 * HW_;
    const __half* vp = qp + (size_t)512 * HW_;
    int tid = threadIdx.x, lane = tid & 31, wid = tid >> 5;
    int g = lane >> 2, tg = lane & 3;
    int rb = wid * 16;

    for (int u = tid; u < 576; u += 192) {
        int row = u / 6, grp = u % 6;
        const __half* sq = qp + row * 96 + grp * 16;
        uint4 x0 = *(const uint4*)sq, x1 = *(const uint4*)(sq + 8);
        *(uint4*)&sQ[row * SQ_PITCH + grp * 8]     = make_uint4(x0.x, x1.x, x0.y, x1.y);
        *(uint4*)&sQ[row * SQ_PITCH + grp * 8 + 4] = make_uint4(x0.z, x1.z, x0.w, x1.w);
        const __half* sk = kp + row * 96 + grp * 16;
        uint4 k0 = *(const uint4*)sk, k1 = *(const uint4*)(sk + 8);
        *(uint4*)&sK[row * SQ_PITCH + grp * 8]     = make_uint4(k0.x, k1.x, k0.y, k1.y);
        *(uint4*)&sK[row * SQ_PITCH + grp * 8 + 4] = make_uint4(k0.z, k1.z, k0.w, k1.w);
    }
    for (int u = tid; u < 288; u += 192) {
        int j2 = u / 6, grp = u % 6;
        const __half* r0 = vp + (2 * j2) * 96 + grp * 16;
        const __half* r1 = r0 + 96;
        uint4 a0 = *(const uint4*)r0, a1 = *(const uint4*)(r0 + 8);
        uint4 b0 = *(const uint4*)r1, b1 = *(const uint4*)(r1 + 8);
        unsigned o[16];
        o[0] = __byte_perm(a0.x, b0.x, 0x5410); o[1] = __byte_perm(a0.x, b0.x, 0x7632);
        o[2] = __byte_perm(a0.y, b0.y, 0x5410); o[3] = __byte_perm(a0.y, b0.y, 0x7632);
        o[4] = __byte_perm(a0.z, b0.z, 0x5410); o[5] = __byte_perm(a0.z, b0.z, 0x7632);
        o[6] = __byte_perm(a0.w, b0.w, 0x5410); o[7] = __byte_perm(a0.w, b0.w, 0x7632);
        o[8] = __byte_perm(a1.x, b1.x, 0x5410); o[9] = __byte_perm(a1.x, b1.x, 0x7632);
        o[10]= __byte_perm(a1.y, b1.y, 0x5410); o[11]= __byte_perm(a1.y, b1.y, 0x7632);
        o[12]= __byte_perm(a1.z, b1.z, 0x5410); o[13]= __byte_perm(a1.z, b1.z, 0x7632);
        o[14]= __byte_perm(a1.w, b1.w, 0x5410); o[15]= __byte_perm(a1.w, b1.w, 0x7632);
        unsigned* dst = (unsigned*)&sV[j2 * SV_PITCH + grp * 16];
        *(uint4*)(dst)      = make_uint4(o[0], o[1], o[2], o[3]);
        *(uint4*)(dst + 4)  = make_uint4(o[4], o[5], o[6], o[7]);
        *(uint4*)(dst + 8)  = make_uint4(o[8], o[9], o[10], o[11]);
        *(uint4*)(dst + 12) = make_uint4(o[12], o[13], o[14], o[15]);
    }
    __syncthreads();

    float sc[12][4] = {};
    #pragma unroll
    for (int kc = 0; kc < 6; kc++) {
        uint2 qa = *(const uint2*)&sQ[(rb + g) * SQ_PITCH + kc * 8 + 2 * tg];
        uint2 qb = *(const uint2*)&sQ[(rb + g + 8) * SQ_PITCH + kc * 8 + 2 * tg];
        #pragma unroll
        for (int ni = 0; ni < 12; ni++) {
            uint2 kb = *(const uint2*)&sK[(ni * 8 + g) * SQ_PITCH + kc * 8 + 2 * tg];
            mma16(sc[ni], qa.x, qb.x, qa.y, qb.y, kb.x, kb.y);
        }
    }
    float m1 = -1e30f, m2 = -1e30f;
    #pragma unroll
    for (int ni = 0; ni < 12; ni++) {
        m1 = fmaxf(m1, fmaxf(sc[ni][0], sc[ni][1]));
        m2 = fmaxf(m2, fmaxf(sc[ni][2], sc[ni][3]));
    }
    m1 = fmaxf(m1, __shfl_xor_sync(0xffffffffu, m1, 1));
    m1 = fmaxf(m1, __shfl_xor_sync(0xffffffffu, m1, 2));
    m2 = fmaxf(m2, __shfl_xor_sync(0xffffffffu, m2, 1));
    m2 = fmaxf(m2, __shfl_xor_sync(0xffffffffu, m2, 2));
    float s1 = 0.f, s2 = 0.f;
    #pragma unroll
    for (int ni = 0; ni < 12; ni++) {
        sc[ni][0] = __expf((sc[ni][0] - m1) * 0.0625f);
        sc[ni][1] = __expf((sc[ni][1] - m1) * 0.0625f);
        sc[ni][2] = __expf((sc[ni][2] - m2) * 0.0625f);
        sc[ni][3] = __expf((sc[ni][3] - m2) * 0.0625f);
        s1 += sc[ni][0] + sc[ni][1];
        s2 += sc[ni][2] + sc[ni][3];
    }
    s1 += __shfl_xor_sync(0xffffffffu, s1, 1);
    s1 += __shfl_xor_sync(0xffffffffu, s1, 2);
    s2 += __shfl_xor_sync(0xffffffffu, s2, 1);
    s2 += __shfl_xor_sync(0xffffffffu, s2, 2);
    float i1 = 1.f / s1, i2 = 1.f / s2;
    unsigned pa[12], pb[12];
    #pragma unroll
    for (int ni = 0; ni < 12; ni++) {
        pa[ni] = packh2(sc[ni][0] * i1, sc[ni][1] * i1);
        pb[ni] = packh2(sc[ni][2] * i2, sc[ni][3] * i2);
    }
    float oc_[12][4] = {};
    #pragma unroll
    for (int kc = 0; kc < 6; kc++) {
        unsigned a0 = pa[2 * kc], a1 = pb[2 * kc];
        unsigned a2 = pa[2 * kc + 1], a3 = pb[2 * kc + 1];
        #pragma unroll
        for (int ni = 0; ni < 12; ni++) {
            unsigned b0 = *(const unsigned*)&sV[(kc * 8 + tg) * SV_PITCH + ni * 8 + g];
            unsigned b1 = *(const unsigned*)&sV[(kc * 8 + tg + 4) * SV_PITCH + ni * 8 + g];
            mma16(oc_[ni], a0, a1, a2, a3, b0, b1);
        }
    }
    int n = c >> 5, d = c & 31, oc = d * 8 + n;
    __half* op = aout + (size_t)(b * C_ + oc) * HW_;
    #pragma unroll
    for (int ni = 0; ni < 12; ni++) {
        int col = ni * 8 + 2 * tg;
        *(__half2*)&op[(rb + g) * 96 + col]     = __floats2half2_rn(oc_[ni][0], oc_[ni][1]);
        *(__half2*)&op[(rb + g + 8) * 96 + col] = __floats2half2_rn(oc_[ni][2], oc_[ni][3]);
    }
}

// ------------------------- fused depthwise 3x3 (x3) + gelu (fp16 in/out) ---
__global__ __launch_bounds__(256) void dwgelu_k(const __half* __restrict__ x,
                                                const float* __restrict__ dww,
                                                const float* __restrict__ dwb,
                                                __half* __restrict__ g) {
    __shared__ float sIn[4][1156];
    __shared__ float sWd[3][36];
    __shared__ float sB[3];
    int tile = blockIdx.x, gch = blockIdx.y, b = blockIdx.z;
    int tx0 = (tile % 3) * 32, ty0 = (tile / 3) * 32;
    int tid = threadIdx.x, col = tid & 31, rowg = tid >> 5;

    for (int idx = tid; idx < 4 * 1156; idx += 256) {
        int ci = idx / 1156, rem = idx - ci * 1156;
        int r = rem / 34, cc = rem - r * 34;
        int gy = ty0 + r - 1, gx = tx0 + cc - 1;
        float v = 0.f;
        if (gy >= 0 && gy < H_ && gx >= 0 && gx < W_)
            v = __half2float(x[((size_t)(b * C_ + gch * 4 + ci)) * HW_ + gy * W_ + gx]);
        sIn[ci][rem] = v;
    }
    for (int idx = tid; idx < 108; idx += 256) {
        int i3 = idx / 36, rem = idx - i3 * 36;
        sWd[i3][rem] = dww[(size_t)(i3 * 64 + gch) * 36 + rem];
    }
    if (tid < 3) sB[tid] = dwb[tid * 64 + gch];
    __syncthreads();

    float acc[3][4];
    #pragma unroll
    for (int i3 = 0; i3 < 3; i3++)
        #pragma unroll
        for (int p = 0; p < 4; p++) acc[i3][p] = 0.f;

    #pragma unroll
    for (int ci = 0; ci < 4; ci++)
        #pragma unroll
        for (int kh = 0; kh < 3; kh++)
            #pragma unroll
            for (int kw = 0; kw < 3; kw++) {
                float iv[4];
                #pragma unroll
                for (int p = 0; p < 4; p++)
                    iv[p] = sIn[ci][(rowg + 8 * p + kh) * 34 + col + kw];
                #pragma unroll
                for (int i3 = 0; i3 < 3; i3++) {
                    float wv = sWd[i3][ci * 9 + kh * 3 + kw];
                    #pragma unroll
                    for (int p = 0; p < 4; p++) acc[i3][p] = fmaf(wv, iv[p], acc[i3][p]);
                }
            }
    #pragma unroll
    for (int i3 = 0; i3 < 3; i3++)
        #pragma unroll
        for (int p = 0; p < 4; p++)
            g[((size_t)(b * 192 + i3 * 64 + gch)) * HW_ + (ty0 + rowg + 8 * p) * W_ + tx0 + col]
                = __float2half_rn(gelu_f(acc[i3][p] + sB[i3]));
}

// ------------------------- freq prep: softmax folded, packed fp16 ----------
__global__ void freqprep_k(const float* __restrict__ fwraw, const float* __restrict__ pww,
                           const float* __restrict__ pwb, __half2* __restrict__ wpk,
                           float* __restrict__ bcomb) {
    float f0 = fwraw[0], f1 = fwraw[1], f2 = fwraw[2];
    float m = fmaxf(f0, fmaxf(f1, f2));
    float e0 = expf(f0 - m), e1 = expf(f1 - m), e2 = expf(f2 - m);
    float inv = 1.f / (e0 + e1 + e2);
    float fw[3] = {e0 * inv, e1 * inv, e2 * inv};
    const int total = 256 * 6 * 16;
    for (int idx = blockIdx.x * 256 + threadIdx.x; idx < total; idx += gridDim.x * 256) {
        int j = idx & 7;
        int kc = (idx >> 3) & 1;
        int rest = idx >> 4;
        int k0c = rest % 6;
        int co = rest / 6;
        int k = k0c * 32 + kc * 16 + perm8inv(j);
        int i = k >> 6, ci = k & 63, ci2 = (k + 8) & 63;
        float a = fw[i] * pww[((size_t)i * C_ + co) * 64 + ci];
        float b = fw[i] * pww[((size_t)i * C_ + co) * 64 + ci2];
        wpk[idx] = __floats2half2_rn(a, b);
    }
    if (blockIdx.x == 0)
        for (int idx = threadIdx.x; idx < C_; idx += 256)
            bcomb[idx] = fw[0] * pwb[idx] + fw[1] * pwb[C_ + idx] + fw[2] * pwb[2 * C_ + idx];
}

// ------------------------- final combine (float4) --------------------------
__global__ void final_k(const float* __restrict__ x, const float* __restrict__ h2,
                        const float* __restrict__ mean2, const float* __restrict__ var2,
                        const float* __restrict__ ag2, const float* __restrict__ ab2,
                        const float* __restrict__ gamma2, const float* __restrict__ beta2,
                        const float* __restrict__ o2, const float* __restrict__ route,
                        float* __restrict__ out) {
    int idx = (blockIdx.x * 256 + threadIdx.x) * 4;
    int bc = idx / HW_;
    int b = bc >> 8, c = bc & 255;
    float r0 = route[2 * b], r1 = route[2 * b + 1];
    float rs = rsqrtf(var2[bc] + EPSF);
    float sc = r0 * (1.f + ag2[bc]) * gamma2[c] * rs;
    float sh = r0 * (ab2[bc] * beta2[c]) - sc * mean2[bc];
    float4 xv = *(const float4*)(x + idx);
    float4 hv = *(const float4*)(h2 + idx);
    float4 ov = *(const float4*)(o2 + idx);
    float4 res;
    res.x = fmaf(sc, hv.x, fmaf(r1, ov.x, xv.x + sh));
    res.y = fmaf(sc, hv.y, fmaf(r1, ov.y, xv.y + sh));
    res.z = fmaf(sc, hv.z, fmaf(r1, ov.z, xv.z + sh));
    res.w = fmaf(sc, hv.w, fmaf(r1, ov.w, xv.w + sh));
    *(float4*)(out + idx) = res;
}

// ===========================================================================
extern "C" void kernel_launch(void* const* d_in, const int* in_sizes, int n_in,
                              void* d_out, int out_size) {
    const float* x     = (const float*)d_in[0];
    const float* w1    = (const float*)d_in[1];
    const float* b1    = (const float*)d_in[2];
    const float* g1    = (const float*)d_in[3];
    const float* be1   = (const float*)d_in[4];
    const float* s1w1  = (const float*)d_in[5];
    const float* s1b1  = (const float*)d_in[6];
    const float* s2w1  = (const float*)d_in[7];
    const float* s2b1  = (const float*)d_in[8];
    const float* w2    = (const float*)d_in[9];
    const float* b2    = (const float*)d_in[10];
    const float* g2    = (const float*)d_in[11];
    const float* be2   = (const float*)d_in[12];
    const float* s1w2  = (const float*)d_in[13];
    const float* s1b2  = (const float*)d_in[14];
    const float* s2w2  = (const float*)d_in[15];
    const float* s2b2  = (const float*)d_in[16];
    const float* qkvw  = (const float*)d_in[17];
    const float* qkvb  = (const float*)d_in[18];
    const float* projw = (const float*)d_in[19];
    const float* projb = (const float*)d_in[20];
    const float* dww   = (const float*)d_in[21];
    const float* dwb   = (const float*)d_in[22];
    const float* pww   = (const float*)d_in[23];
    const float* pwb   = (const float*)d_in[24];
    const float* fwr   = (const float*)d_in[25];
    const float* rw    = (const float*)d_in[26];
    const float* rb    = (const float*)d_in[27];
    float* out = (float*)d_out;

    float *h1, *h2, *o2, *pooledx, *route;
    float *mean1, *var1, *ag1, *ab1, *mean2, *var2, *ag2, *ab2, *bcomb;
    __half *xh, *h1g, *qkvh, *ah, *gh;
    __half2 *wpkq, *wpkp, *wpkc;
    cudaGetSymbolAddress((void**)&xh,  g_xh);
    cudaGetSymbolAddress((void**)&h1,  g_h1);
    cudaGetSymbolAddress((void**)&h2,  g_h2);
    cudaGetSymbolAddress((void**)&o2,  g_o2);
    cudaGetSymbolAddress((void**)&h1g, g_h1g);
    cudaGetSymbolAddress((void**)&qkvh, g_qkv);
    cudaGetSymbolAddress((void**)&ah,  g_a);
    cudaGetSymbolAddress((void**)&gh,  g_g);
    cudaGetSymbolAddress((void**)&pooledx, g_pooledx);
    cudaGetSymbolAddress((void**)&route,   g_route);
    cudaGetSymbolAddress((void**)&mean1, g_mean1);
    cudaGetSymbolAddress((void**)&var1,  g_var1);
    cudaGetSymbolAddress((void**)&ag1,   g_ag1);
    cudaGetSymbolAddress((void**)&ab1,   g_ab1);
    cudaGetSymbolAddress((void**)&mean2, g_mean2);
    cudaGetSymbolAddress((void**)&var2,  g_var2);
    cudaGetSymbolAddress((void**)&ag2,   g_ag2);
    cudaGetSymbolAddress((void**)&ab2,   g_ab2);
    cudaGetSymbolAddress((void**)&bcomb, g_bcomb);
    cudaGetSymbolAddress((void**)&wpkq,  g_wpkq);
    cudaGetSymbolAddress((void**)&wpkp,  g_wpkp);
    cudaGetSymbolAddress((void**)&wpkc,  g_wpkc);

    const int attnSmem = (2 * 96 * SQ_PITCH + 48 * SV_PITCH) * 4;
    cudaFuncSetAttribute(attn_h, cudaFuncAttributeMaxDynamicSharedMemorySize, attnSmem);

    static cudaStream_t s2 = nullptr;
    static cudaEvent_t evFork = nullptr, evJoin = nullptr;
    if (!s2) {
        cudaStreamCreateWithFlags(&s2, cudaStreamNonBlocking);
        cudaEventCreateWithFlags(&evFork, cudaEventDisableTiming);
        cudaEventCreateWithFlags(&evJoin, cudaEventDisableTiming);
    }

    // x -> fp16 + pooled mean; router  [stream 0]
    xcvt_k<<<B_ * C_, 256>>>(x, xh, pooledx);
    router_k<<<1, 32>>>(pooledx, rw, rb, route);

    // fork: branch 2 runs on s2, branch 1 stays on stream 0
    cudaEventRecord(evFork, 0);
    cudaStreamWaitEvent(s2, evFork, 0);

    // branch 1 [stream 0]  (convs identical to R15)
    conv3x3_h<256, 64><<<dim3(48, 1, B_), 256>>>(xh, w1, b1, h1);
    reduce_stats_k<<<B_ * C4_, 256>>>(h1, mean1, var1);
    se_k<<<B_, 256>>>(mean1, s1w1, s1b1, s2w1, s2b1, ag1, ab1, C4_, 16);
    afngelu_k<<<(B_ * C4_ * HW_) / 1024, 256>>>(h1, mean1, var1, ag1, ab1, g1, be1, h1g, C4_);
    conv3x3_h<64, 256><<<dim3(48, 4, B_), 256>>>(h1g, w2, b2, h2);
    reduce_stats_k<<<B_ * C_, 256>>>(h2, mean2, var2);
    se_k<<<B_, 256>>>(mean2, s1w2, s1b2, s2w2, s2b2, ag2, ab2, C_, 64);

    // branch 2 [stream s2]: prepacks overlap with branch-1 conv1
    prepgemm_k<<<96, 256, 0, s2>>>(qkvw, wpkq, 256, 768);
    prepgemm_k<<<32, 256, 0, s2>>>(projw, wpkp, 256, 256);
    gemm1x1_h<__half, false><<<dim3(36, 12, B_), 256, 0, s2>>>(xh, wpkq, qkvb, qkvh, 256, 768);
    attn_h<<<dim3(256, B_), 192, attnSmem, s2>>>(qkvh, ah);
    gemm1x1_h<float, false><<<dim3(36, 4, B_), 256, 0, s2>>>(ah, wpkp, projb, o2, 256, 256);
    freqprep_k<<<24, 256, 0, s2>>>(fwr, pww, pwb, wpkc, bcomb);
    dwgelu_k<<<dim3(9, 64, B_), 256, 0, s2>>>(xh, dww, dwb, gh);
    gemm1x1_h<float, true><<<dim3(36, 4, B_), 256, 0, s2>>>(gh, wpkc, bcomb, o2, 192, 256);

    // join: stream 0 waits for branch 2 before final combine
    cudaEventRecord(evJoin, s2);
    cudaStreamWaitEvent(0, evJoin, 0);

    // final combine [stream 0]
    final_k<<<(B_ * C_ * HW_) / 1024, 256>>>(x, h2, mean2, var2, ag2, ab2, g2, be2,
                                             o2, route, out);
}